// round 5
// baseline (speedup 1.0000x reference)
#include <cuda_runtime.h>
#include <math.h>

// ---------------------------------------------------------------------------
// Problem constants
// ---------------------------------------------------------------------------
#define BATCH   64
#define TFULL   512
#define THARM   256
#define TSPIKE  256
#define NINP    64
#define NHID    1024
#define DTF     0.042f
#define THRESH  0.008f
#define RESETV  0.001f
#define LEAKC   0.00105f      /* R_MEM * C_MEM * DT = 5 * 0.005 * 0.042 */

// ---------------------------------------------------------------------------
// Device scratch (static — no cudaMalloc anywhere)
// ---------------------------------------------------------------------------
__device__ float g_xw[(size_t)THARM * BATCH * NHID];  // x @ x2h for t<256 (64 MB)
__device__ float g_hyT[2][NHID * BATCH];              // hy state, transposed [j][b]
__device__ float g_hz [BATCH * NHID];                 // hz state [b][h]
__device__ float g_hyW[BATCH * NHID];                 // hy_final @ h2h  [b][h]

// ---------------------------------------------------------------------------
// packed f32x2 FMA helpers (FFMA2 only reachable via PTX fma.rn.f32x2)
// ---------------------------------------------------------------------------
__device__ __forceinline__ unsigned long long pk2(float lo, float hi) {
    unsigned long long r;
    asm("mov.b64 %0, {%1, %2};" : "=l"(r) : "f"(lo), "f"(hi));
    return r;
}
__device__ __forceinline__ void upk2(unsigned long long v, float &lo, float &hi) {
    asm("mov.b64 {%0, %1}, %2;" : "=f"(lo), "=f"(hi) : "l"(v));
}
__device__ __forceinline__ void fma2(unsigned long long &d,
                                     unsigned long long a,
                                     unsigned long long b) {
    asm("fma.rn.f32x2 %0, %1, %2, %0;" : "+l"(d) : "l"(a), "l"(b));
}

// ---------------------------------------------------------------------------
// init: zero hy (buffer 0, transposed) and hz state
// ---------------------------------------------------------------------------
__global__ void __launch_bounds__(256)
init_kernel() {
    int i = blockIdx.x * 256 + threadIdx.x;   // grid 256 -> 65536 threads
    g_hyT[0][i] = 0.0f;
    g_hz[i]     = 0.0f;
}

// ---------------------------------------------------------------------------
// xw[t][b][h] = x[b,t,:] @ x2h[:,h]   for t in [0,256)
// grid = 256 (one block per t), 256 threads (each owns 4 h columns)
// ---------------------------------------------------------------------------
__global__ void __launch_bounds__(256)
xw_kernel(const float* __restrict__ x, const float* __restrict__ x2h) {
    __shared__ float2 x_s[BATCH * NINP];   // duplicated (v,v) pairs, 32 KB

    const int t   = blockIdx.x;
    const int tid = threadIdx.x;

    for (int i = tid; i < BATCH * NINP; i += 256) {
        int b = i >> 6, ii = i & 63;
        float v = x[((size_t)b * TFULL + t) * NINP + ii];
        x_s[i] = make_float2(v, v);
    }
    __syncthreads();

    const int h0 = tid * 4;

    for (int bg = 0; bg < 8; bg++) {               // 8 groups of 8 batches
        unsigned long long acc[8][2];
        #pragma unroll
        for (int bb = 0; bb < 8; bb++) { acc[bb][0] = 0ull; acc[bb][1] = 0ull; }

        #pragma unroll 4
        for (int k = 0; k < NINP; k++) {
            ulonglong2 w = *(const ulonglong2*)&x2h[k * NHID + h0];
            #pragma unroll
            for (int bb = 0; bb < 8; bb++) {
                unsigned long long xv =
                    *(const unsigned long long*)&x_s[(bg * 8 + bb) * NINP + k];
                fma2(acc[bb][0], xv, w.x);
                fma2(acc[bb][1], xv, w.y);
            }
        }
        #pragma unroll
        for (int bb = 0; bb < 8; bb++) {
            int b = bg * 8 + bb;
            float o0, o1, o2, o3;
            upk2(acc[bb][0], o0, o1);
            upk2(acc[bb][1], o2, o3);
            *(float4*)&g_xw[((size_t)t * BATCH + b) * NHID + h0] =
                make_float4(o0, o1, o2, o3);
        }
    }
}

// ---------------------------------------------------------------------------
// core matvec: acc[0..3] = hyT_in @ W  for this thread's (b, j0..j0+3)
// hyT_in layout: [k][b] (k-major, b fastest). W row-major [k][NHID].
// Block = 128 threads: b = tid&63, jq = tid>>6; CTA covers 8 j-columns.
// ---------------------------------------------------------------------------
__device__ __forceinline__ void matvec8(const float* __restrict__ hyT_in,
                                        const float* __restrict__ W,
                                        float* __restrict__ hy_s,   // [128*64]
                                        int tid, int b, int j0,
                                        float acc[4]) {
    unsigned long long a0 = 0ull, a1 = 0ull;
    const float* wb = W + j0;

    for (int kc = 0; kc < NHID / 128; kc++) {
        __syncthreads();
        {   // stage 128 k-rows x 64 b = 32 KB, fully coalesced float4
            const float4* src = (const float4*)(hyT_in + (size_t)kc * 128 * 64);
            float4* dst = (float4*)hy_s;
            #pragma unroll
            for (int i = tid; i < 128 * 64 / 4; i += 128)
                dst[i] = __ldg(&src[i]);
        }
        __syncthreads();

        #pragma unroll 8
        for (int k = 0; k < 128; k++) {
            float hv = hy_s[k * 64 + b];
            unsigned long long hp = pk2(hv, hv);
            ulonglong2 w = *(const ulonglong2*)(wb + (size_t)(kc * 128 + k) * NHID);
            fma2(a0, hp, w.x);
            fma2(a1, hp, w.y);
        }
    }
    upk2(a0, acc[0], acc[1]);
    upk2(a1, acc[2], acc[3]);
}

// ---------------------------------------------------------------------------
// one harmonic step:
//   hz += DT*(tanh(hy@W + xw + bias) - gamma*hy - eps*hz);  hy += DT*hz
// grid = 128, block = 128
// ---------------------------------------------------------------------------
__global__ void __launch_bounds__(128)
harm_step_kernel(const float* __restrict__ W,
                 const float* __restrict__ bias,
                 const float* __restrict__ gamma,
                 const float* __restrict__ epsv,
                 const float* __restrict__ hyT_in,
                 float* __restrict__ hyT_out,
                 float* __restrict__ hys,
                 float* __restrict__ hzs,
                 int t) {
    __shared__ float hy_s[128 * 64];
    const int tid = threadIdx.x;
    const int b   = tid & 63;
    const int jq  = tid >> 6;
    const int j0  = blockIdx.x * 8 + jq * 4;

    float acc[4];
    matvec8(hyT_in, W, hy_s, tid, b, j0, acc);

    // old state
    float hyo[4];
    #pragma unroll
    for (int q = 0; q < 4; q++) hyo[q] = hyT_in[(size_t)(j0 + q) * 64 + b];
    float4 hzv = *(const float4*)&g_hz[(size_t)b * NHID + j0];
    float hzo[4] = {hzv.x, hzv.y, hzv.z, hzv.w};

    float4 xv  = *(const float4*)&g_xw[((size_t)t * BATCH + b) * NHID + j0];
    float xvq[4] = {xv.x, xv.y, xv.z, xv.w};
    float4 bsv = *(const float4*)&bias[j0];
    float4 gmv = *(const float4*)&gamma[j0];
    float4 epv = *(const float4*)&epsv[j0];
    float bs[4] = {bsv.x, bsv.y, bsv.z, bsv.w};
    float gm[4] = {gmv.x, gmv.y, gmv.z, gmv.w};
    float ep[4] = {epv.x, epv.y, epv.z, epv.w};

    float hyn[4], hzn[4];
    #pragma unroll
    for (int q = 0; q < 4; q++) {
        float pre = acc[q] + xvq[q] + bs[q];
        float val = tanhf(pre);
        hzn[q] = hzo[q] + DTF * ((val - gm[q] * hyo[q]) - ep[q] * hzo[q]);
        hyn[q] = hyo[q] + DTF * hzn[q];
    }

    // new state
    #pragma unroll
    for (int q = 0; q < 4; q++) hyT_out[(size_t)(j0 + q) * 64 + b] = hyn[q];
    *(float4*)&g_hz[(size_t)b * NHID + j0] = make_float4(hzn[0], hzn[1], hzn[2], hzn[3]);

    // trajectory outputs (B, T, H)
    size_t o = ((size_t)b * TFULL + t) * NHID + j0;
    *(float4*)&hys[o] = make_float4(hyn[0], hyn[1], hyn[2], hyn[3]);
    *(float4*)&hzs[o] = make_float4(hzn[0], hzn[1], hzn[2], hzn[3]);
}

// ---------------------------------------------------------------------------
// hyW = hy_final @ W   (no state update) — grid 128, block 128
// ---------------------------------------------------------------------------
__global__ void __launch_bounds__(128)
hyw_kernel(const float* __restrict__ W,
           const float* __restrict__ hyT_in) {
    __shared__ float hy_s[128 * 64];
    const int tid = threadIdx.x;
    const int b   = tid & 63;
    const int jq  = tid >> 6;
    const int j0  = blockIdx.x * 8 + jq * 4;

    float acc[4];
    matvec8(hyT_in, W, hy_s, tid, b, j0, acc);

    *(float4*)&g_hyW[(size_t)b * NHID + j0] =
        make_float4(acc[0], acc[1], acc[2], acc[3]);
}

// ---------------------------------------------------------------------------
// spiking LIF phase + constant tails of hys/hzs for t in [256,512)
// grid = 256, block = 256 -> one thread per (b, h)
// ---------------------------------------------------------------------------
__global__ void __launch_bounds__(256)
spike_kernel(float* __restrict__ us,
             float* __restrict__ spk,
             float* __restrict__ hys,
             float* __restrict__ hzs) {
    const int gid = blockIdx.x * 256 + threadIdx.x;  // 0..65535
    const int b = gid >> 10;
    const int h = gid & 1023;

    const float hyw = g_hyW[gid];
    const float hyf = __ldg(&g_hyT[0][(size_t)h * 64 + b]);  // final hy (buf 0 after 256 steps)
    const float hzf = g_hz[gid];

    const float* xp  = g_xw + (size_t)b * NHID + h;                  // + t*B*NHID
    float* up  = us  + (size_t)b * TSPIKE * NHID + h;                // + t*NHID
    float* sp  = spk + (size_t)b * TSPIKE * NHID + h;
    float* hyp = hys + ((size_t)b * TFULL + THARM) * NHID + h;
    float* hzp = hzs + ((size_t)b * TFULL + THARM) * NHID + h;

    float u = 0.0f;
    #pragma unroll 4
    for (int t = 0; t < TSPIKE; t++) {
        float s = (u > THRESH) ? 1.0f : 0.0f;
        if (u > THRESH) u = RESETV;
        float xin = __ldg(xp + (size_t)t * BATCH * NHID);
        u = u + ((hyw + xin) - u) * LEAKC;
        up[(size_t)t * NHID]  = u;
        sp[(size_t)t * NHID]  = s;
        hyp[(size_t)t * NHID] = hyf;
        hzp[(size_t)t * NHID] = hzf;
    }
}

// ---------------------------------------------------------------------------
// launcher: init -> xw -> 256 x harm_step -> hyw -> spike
// ---------------------------------------------------------------------------
extern "C" void kernel_launch(void* const* d_in, const int* in_sizes, int n_in,
                              void* d_out, int out_size) {
    const float* x    = (const float*)d_in[0];
    const float* x2h  = (const float*)d_in[1];
    const float* h2h  = (const float*)d_in[2];
    const float* bias = (const float*)d_in[3];
    const float* gam  = (const float*)d_in[4];
    const float* eps  = (const float*)d_in[5];

    float* out = (float*)d_out;
    float* hys = out;                                            // B*T*H
    float* hzs = hys + (size_t)BATCH * TFULL * NHID;             // B*T*H
    float* us  = hzs + (size_t)BATCH * TFULL * NHID;             // B*Ts*H
    float* spk = us  + (size_t)BATCH * TSPIKE * NHID;            // B*Ts*H

    float* hyT0;
    float* hyT1;
    cudaGetSymbolAddress((void**)&hyT0, g_hyT);
    hyT1 = hyT0 + NHID * BATCH;

    init_kernel<<<256, 256>>>();
    xw_kernel<<<THARM, 256>>>(x, x2h);

    for (int t = 0; t < THARM; t++) {
        float* in  = (t & 1) ? hyT1 : hyT0;
        float* outb = (t & 1) ? hyT0 : hyT1;
        harm_step_kernel<<<128, 128>>>(h2h, bias, gam, eps, in, outb,
                                       hys, hzs, t);
    }
    // after 256 steps final hy lives in buffer 0
    hyw_kernel<<<128, 128>>>(h2h, hyT0);
    spike_kernel<<<256, 256>>>(us, spk, hys, hzs);
}

// round 6
// speedup vs baseline: 2.6409x; 2.6409x over previous
#include <cuda_runtime.h>
#include <cuda_pipeline.h>
#include <math.h>

// ---------------------------------------------------------------------------
// Problem constants
// ---------------------------------------------------------------------------
#define BATCH   64
#define TFULL   512
#define THARM   256
#define TSPIKE  256
#define NINP    64
#define NHID    1024
#define DTF     0.042f
#define THRESH  0.008f
#define RESETV  0.001f
#define LEAKC   0.00105f      /* R_MEM * C_MEM * DT = 5 * 0.005 * 0.042 */

#define GRID_H  128           /* persistent CTAs, 8 h-cols each            */
#define BLK_H   128           /* threads per CTA: b = tid&63, jq = tid>>6  */

// ---------------------------------------------------------------------------
// Device scratch (static — no cudaMalloc anywhere)
// ---------------------------------------------------------------------------
__device__ float    g_xw[(size_t)THARM * BATCH * NHID]; // x @ x2h, t<256 (64 MB)
__device__ float    g_hyT[2][NHID * BATCH];             // hy exchange, [j][b]
__device__ float    g_hzF[BATCH * NHID];                // final hz [b][h]
__device__ float    g_hyW[BATCH * NHID];                // hy_final @ h2h [b][h]
__device__ unsigned g_bar;                              // grid barrier counter

// ---------------------------------------------------------------------------
// packed f32x2 FMA helpers (FFMA2 only reachable via PTX fma.rn.f32x2)
// ---------------------------------------------------------------------------
__device__ __forceinline__ unsigned long long pk2(float lo, float hi) {
    unsigned long long r;
    asm("mov.b64 %0, {%1, %2};" : "=l"(r) : "f"(lo), "f"(hi));
    return r;
}
__device__ __forceinline__ void upk2(unsigned long long v, float &lo, float &hi) {
    asm("mov.b64 {%0, %1}, %2;" : "=f"(lo), "=f"(hi) : "l"(v));
}
__device__ __forceinline__ void fma2(unsigned long long &d,
                                     unsigned long long a,
                                     unsigned long long b) {
    asm("fma.rn.f32x2 %0, %1, %2, %0;" : "+l"(d) : "l"(a), "l"(b));
}

// ---------------------------------------------------------------------------
// init: zero hy buffer 0 (transposed) and the barrier counter
// ---------------------------------------------------------------------------
__global__ void __launch_bounds__(256)
init_kernel() {
    int i = blockIdx.x * 256 + threadIdx.x;     // grid 256 -> 65536
    g_hyT[0][i] = 0.0f;
    if (i == 0) g_bar = 0u;
}

// ---------------------------------------------------------------------------
// xw[t][b][h] = x[b,t,:] @ x2h[:,h]  for t in [0,256).  grid=256, blk=256.
// ---------------------------------------------------------------------------
__global__ void __launch_bounds__(256)
xw_kernel(const float* __restrict__ x, const float* __restrict__ x2h) {
    __shared__ float2 x_s[BATCH * NINP];     // duplicated (v,v) pairs, 32 KB

    const int t   = blockIdx.x;
    const int tid = threadIdx.x;

    for (int i = tid; i < BATCH * NINP; i += 256) {
        int b = i >> 6, ii = i & 63;
        float v = x[((size_t)b * TFULL + t) * NINP + ii];
        x_s[i] = make_float2(v, v);
    }
    __syncthreads();

    const int h0 = tid * 4;

    for (int bg = 0; bg < 8; bg++) {
        unsigned long long acc[8][2];
        #pragma unroll
        for (int bb = 0; bb < 8; bb++) { acc[bb][0] = 0ull; acc[bb][1] = 0ull; }

        #pragma unroll 4
        for (int k = 0; k < NINP; k++) {
            ulonglong2 w = *(const ulonglong2*)&x2h[k * NHID + h0];
            #pragma unroll
            for (int bb = 0; bb < 8; bb++) {
                unsigned long long xv =
                    *(const unsigned long long*)&x_s[(bg * 8 + bb) * NINP + k];
                fma2(acc[bb][0], xv, w.x);
                fma2(acc[bb][1], xv, w.y);
            }
        }
        #pragma unroll
        for (int bb = 0; bb < 8; bb++) {
            int b = bg * 8 + bb;
            float o0, o1, o2, o3;
            upk2(acc[bb][0], o0, o1);
            upk2(acc[bb][1], o2, o3);
            *(float4*)&g_xw[((size_t)t * BATCH + b) * NHID + h0] =
                make_float4(o0, o1, o2, o3);
        }
    }
}

// ---------------------------------------------------------------------------
// matvec of one hyT buffer against this CTA's resident W columns.
// hyT layout [k][b]; staged through double-buffered smem via cp.async.cg.
// ---------------------------------------------------------------------------
__device__ __forceinline__ void matvec_resident(const float* __restrict__ hyIn,
                                                const float* __restrict__ w_s,
                                                float* __restrict__ buf0,
                                                float* __restrict__ buf1,
                                                int tid, int b, int jq,
                                                unsigned long long &a0,
                                                unsigned long long &a1) {
    // prologue: stage chunk 0
    {
        const float4* src = (const float4*)hyIn;
        float4* dst = (float4*)buf0;
        #pragma unroll
        for (int i = tid; i < 2048; i += BLK_H)
            __pipeline_memcpy_async(&dst[i], &src[i], 16);
        __pipeline_commit();
    }
    for (int c = 0; c < 8; c++) {
        float* cur = (c & 1) ? buf1 : buf0;
        if (c < 7) {
            float* nxt = (c & 1) ? buf0 : buf1;
            const float4* src = (const float4*)(hyIn + (size_t)(c + 1) * 8192);
            float4* dst = (float4*)nxt;
            #pragma unroll
            for (int i = tid; i < 2048; i += BLK_H)
                __pipeline_memcpy_async(&dst[i], &src[i], 16);
            __pipeline_commit();
            __pipeline_wait_prior(1);
        } else {
            __pipeline_wait_prior(0);
        }
        __syncthreads();                  // chunk c visible to all warps

        const float* ws = w_s + (size_t)c * 128 * 8 + jq * 4;
        #pragma unroll 8
        for (int k = 0; k < 128; k++) {
            float hv = cur[k * 64 + b];
            unsigned long long hp = pk2(hv, hv);
            ulonglong2 w = *(const ulonglong2*)(ws + k * 8);
            fma2(a0, hp, w.x);
            fma2(a1, hp, w.y);
        }
        __syncthreads();                  // done with cur before it's re-filled
    }
}

// ---------------------------------------------------------------------------
// persistent harmonic kernel: 256 steps with a software grid barrier.
// grid = 128, block = 128, dynamic smem = 96 KB (W 32K + 2 x 32K staging).
// ---------------------------------------------------------------------------
__global__ void __launch_bounds__(BLK_H, 1)
harm_persist(const float* __restrict__ W,
             const float* __restrict__ bias,
             const float* __restrict__ gamma,
             const float* __restrict__ epsv,
             float* __restrict__ hys,
             float* __restrict__ hzs) {
    extern __shared__ float sm[];
    float* w_s  = sm;                 // [1024][8]  32 KB
    float* buf0 = sm + NHID * 8;      // [128][64]  32 KB
    float* buf1 = buf0 + 128 * 64;    // [128][64]  32 KB

    const int tid = threadIdx.x;
    const int b   = tid & 63;
    const int jq  = tid >> 6;                 // 0 or 1
    const int J0  = blockIdx.x * 8;
    const int j0  = J0 + jq * 4;

    // one-time: stage this CTA's 8 W columns into smem, layout [k][8]
    for (int i = tid; i < NHID * 8; i += BLK_H) {
        int k = i >> 3, c = i & 7;
        w_s[i] = W[(size_t)k * NHID + J0 + c];
    }

    float4 bsv = *(const float4*)&bias[j0];
    float4 gmv = *(const float4*)&gamma[j0];
    float4 epv = *(const float4*)&epsv[j0];
    const float bs[4] = {bsv.x, bsv.y, bsv.z, bsv.w};
    const float gm[4] = {gmv.x, gmv.y, gmv.z, gmv.w};
    const float ep[4] = {epv.x, epv.y, epv.z, epv.w};

    float hy[4] = {0.f, 0.f, 0.f, 0.f};
    float hz[4] = {0.f, 0.f, 0.f, 0.f};

    __syncthreads();   // w_s ready

    for (int t = 0; t < THARM; t++) {
        unsigned long long a0 = 0ull, a1 = 0ull;
        if (t > 0) {
            matvec_resident(g_hyT[t & 1], w_s, buf0, buf1, tid, b, jq, a0, a1);
        }

        float acc[4];
        upk2(a0, acc[0], acc[1]);
        upk2(a1, acc[2], acc[3]);

        float4 xv = *(const float4*)&g_xw[((size_t)t * BATCH + b) * NHID + j0];
        const float xvq[4] = {xv.x, xv.y, xv.z, xv.w};

        #pragma unroll
        for (int q = 0; q < 4; q++) {
            float pre = acc[q] + xvq[q] + bs[q];
            float val = tanhf(pre);
            hz[q] = hz[q] + DTF * ((val - gm[q] * hy[q]) - ep[q] * hz[q]);
            hy[q] = hy[q] + DTF * hz[q];
        }

        // publish hy (transposed [j][b]) for the next step
        float* hyOut = g_hyT[(t + 1) & 1];
        #pragma unroll
        for (int q = 0; q < 4; q++)
            hyOut[(size_t)(j0 + q) * 64 + b] = hy[q];

        // trajectory outputs (B, T, H)
        size_t o = ((size_t)b * TFULL + t) * NHID + j0;
        *(float4*)&hys[o] = make_float4(hy[0], hy[1], hy[2], hy[3]);
        *(float4*)&hzs[o] = make_float4(hz[0], hz[1], hz[2], hz[3]);

        // ---- grid barrier ----
        __threadfence();          // publish this thread's hy stores
        __syncthreads();          // all threads' fences done
        if (tid == 0) {
            atomicAdd(&g_bar, 1u);
            unsigned tgt = (unsigned)GRID_H * (unsigned)(t + 1);
            while (*(volatile unsigned*)&g_bar < tgt) __nanosleep(64);
            __threadfence();      // acquire-ish
        }
        __syncthreads();
    }

    // ---- final: hyW = hy_final @ W (buffer 0 holds hy after 256 steps) ----
    {
        unsigned long long a0 = 0ull, a1 = 0ull;
        matvec_resident(g_hyT[0], w_s, buf0, buf1, tid, b, jq, a0, a1);
        float acc[4];
        upk2(a0, acc[0], acc[1]);
        upk2(a1, acc[2], acc[3]);
        #pragma unroll
        for (int q = 0; q < 4; q++) {
            g_hyW[(size_t)b * NHID + j0 + q] = acc[q];
            g_hzF[(size_t)b * NHID + j0 + q] = hz[q];
        }
    }
}

// ---------------------------------------------------------------------------
// spiking LIF phase + constant tails of hys/hzs for t in [256,512)
// grid = 256, block = 256 -> one thread per (b, h)
// ---------------------------------------------------------------------------
__global__ void __launch_bounds__(256)
spike_kernel(float* __restrict__ us,
             float* __restrict__ spk,
             float* __restrict__ hys,
             float* __restrict__ hzs) {
    const int gid = blockIdx.x * 256 + threadIdx.x;   // 0..65535
    const int b = gid >> 10;
    const int h = gid & 1023;

    const float hyw = g_hyW[gid];
    const float hyf = __ldg(&g_hyT[0][(size_t)h * 64 + b]);  // final hy
    const float hzf = g_hzF[gid];

    const float* xp  = g_xw + (size_t)b * NHID + h;
    float* up  = us  + (size_t)b * TSPIKE * NHID + h;
    float* sp  = spk + (size_t)b * TSPIKE * NHID + h;
    float* hyp = hys + ((size_t)b * TFULL + THARM) * NHID + h;
    float* hzp = hzs + ((size_t)b * TFULL + THARM) * NHID + h;

    float u = 0.0f;
    #pragma unroll 4
    for (int t = 0; t < TSPIKE; t++) {
        float s = (u > THRESH) ? 1.0f : 0.0f;
        if (u > THRESH) u = RESETV;
        float xin = __ldg(xp + (size_t)t * BATCH * NHID);
        u = u + ((hyw + xin) - u) * LEAKC;
        up[(size_t)t * NHID]  = u;
        sp[(size_t)t * NHID]  = s;
        hyp[(size_t)t * NHID] = hyf;
        hzp[(size_t)t * NHID] = hzf;
    }
}

// ---------------------------------------------------------------------------
// launcher: init -> xw -> persistent harmonic -> spike
// ---------------------------------------------------------------------------
extern "C" void kernel_launch(void* const* d_in, const int* in_sizes, int n_in,
                              void* d_out, int out_size) {
    const float* x    = (const float*)d_in[0];
    const float* x2h  = (const float*)d_in[1];
    const float* h2h  = (const float*)d_in[2];
    const float* bias = (const float*)d_in[3];
    const float* gam  = (const float*)d_in[4];
    const float* eps  = (const float*)d_in[5];

    float* out = (float*)d_out;
    float* hys = out;                                     // B*T*H
    float* hzs = hys + (size_t)BATCH * TFULL * NHID;      // B*T*H
    float* us  = hzs + (size_t)BATCH * TFULL * NHID;      // B*Ts*H
    float* spk = us  + (size_t)BATCH * TSPIKE * NHID;     // B*Ts*H

    static int smem_set = 0;
    const int smem_bytes = (NHID * 8 + 2 * 128 * 64) * sizeof(float);  // 96 KB
    if (!smem_set) {
        cudaFuncSetAttribute(harm_persist,
                             cudaFuncAttributeMaxDynamicSharedMemorySize,
                             smem_bytes);
        smem_set = 1;
    }

    init_kernel<<<256, 256>>>();
    xw_kernel<<<THARM, 256>>>(x, x2h);
    harm_persist<<<GRID_H, BLK_H, smem_bytes>>>(h2h, bias, gam, eps, hys, hzs);
    spike_kernel<<<256, 256>>>(us, spk, hys, hzs);
}

// round 7
// speedup vs baseline: 3.3498x; 1.2684x over previous
#include <cuda_runtime.h>
#include <math.h>

// ---------------------------------------------------------------------------
// Problem constants
// ---------------------------------------------------------------------------
#define BATCH   64
#define TFULL   512
#define THARM   256
#define TSPIKE  256
#define NINP    64
#define NHID    1024
#define DTF     0.042f
#define THRESH  0.008f
#define RESETV  0.001f
#define LEAKC   0.00105f      /* R_MEM * C_MEM * DT */

#define GRID_H  128           /* persistent CTAs, 8 h-cols each             */
#define BLK_H   128           /* b = tid&63, jq = tid>>6 (k-split half)     */
#define NCH     8             /* chunks per step, 128 k each                */
#define CHF     8192          /* floats per chunk  (128 k x 64 b) = 32 KB   */

// ---------------------------------------------------------------------------
// Device scratch (static — no cudaMalloc anywhere)
// ---------------------------------------------------------------------------
__device__ float    g_xw[(size_t)THARM * BATCH * NHID]; // x @ x2h  (64 MB)
__device__ float    g_hyBK[2][BATCH * NHID];            // hy state [b][k]
__device__ float    g_hzF[BATCH * NHID];                // final hz [b][h]
__device__ float    g_hyW[BATCH * NHID];                // hy_final @ h2h
__device__ unsigned g_flag[NCH];                        // per-chunk epochs

// ---------------------------------------------------------------------------
// packed f32x2 helpers
// ---------------------------------------------------------------------------
__device__ __forceinline__ void upk2(unsigned long long v, float &lo, float &hi) {
    asm("mov.b64 {%0, %1}, %2;" : "=f"(lo), "=f"(hi) : "l"(v));
}
__device__ __forceinline__ void fma2(unsigned long long &d,
                                     unsigned long long a,
                                     unsigned long long b) {
    asm("fma.rn.f32x2 %0, %1, %2, %0;" : "+l"(d) : "l"(a), "l"(b));
}

// ---------------------------------------------------------------------------
// async-copy / flag primitives
// ---------------------------------------------------------------------------
__device__ __forceinline__ void cp_async16(float* dst, const float* src) {
    unsigned d = (unsigned)__cvta_generic_to_shared(dst);
    asm volatile("cp.async.cg.shared.global [%0], [%1], 16;"
                 :: "r"(d), "l"(src));
}
__device__ __forceinline__ void cp_commit() {
    asm volatile("cp.async.commit_group;");
}
template<int N> __device__ __forceinline__ void cp_wait() {
    asm volatile("cp.async.wait_group %0;" :: "n"(N));
}
__device__ __forceinline__ unsigned ld_acq(const unsigned* p) {
    unsigned v;
    asm volatile("ld.acquire.gpu.global.u32 %0, [%1];" : "=r"(v) : "l"(p));
    return v;
}
__device__ __forceinline__ void red_release(unsigned* p) {
    asm volatile("red.release.gpu.global.add.u32 [%0], 1;" :: "l"(p));
}
__device__ __forceinline__ void poll_flag(int c, unsigned tgt) {
    if (ld_acq(&g_flag[c]) >= tgt) return;
    while (ld_acq(&g_flag[c]) < tgt) __nanosleep(40);
}

// ---------------------------------------------------------------------------
// xw[t][b][h] = x[b,t,:] @ x2h[:,h]  for t < 256.  grid=256, blk=256.
// Block 0 also resets the chunk flags for this launch (graph-replay safe).
// ---------------------------------------------------------------------------
__device__ __forceinline__ unsigned long long pk2dup(float v) {
    unsigned long long r;
    asm("mov.b64 %0, {%1, %1};" : "=l"(r) : "f"(v));
    return r;
}

__global__ void __launch_bounds__(256)
xw_kernel(const float* __restrict__ x, const float* __restrict__ x2h) {
    __shared__ float2 x_s[BATCH * NINP];

    const int t   = blockIdx.x;
    const int tid = threadIdx.x;

    if (blockIdx.x == 0 && tid < NCH) g_flag[tid] = 0u;

    for (int i = tid; i < BATCH * NINP; i += 256) {
        int b = i >> 6, ii = i & 63;
        float v = x[((size_t)b * TFULL + t) * NINP + ii];
        x_s[i] = make_float2(v, v);
    }
    __syncthreads();

    const int h0 = tid * 4;

    for (int bg = 0; bg < 8; bg++) {
        unsigned long long acc[8][2];
        #pragma unroll
        for (int bb = 0; bb < 8; bb++) { acc[bb][0] = 0ull; acc[bb][1] = 0ull; }

        #pragma unroll 4
        for (int k = 0; k < NINP; k++) {
            ulonglong2 w = *(const ulonglong2*)&x2h[k * NHID + h0];
            #pragma unroll
            for (int bb = 0; bb < 8; bb++) {
                unsigned long long xv =
                    *(const unsigned long long*)&x_s[(bg * 8 + bb) * NINP + k];
                fma2(acc[bb][0], xv, w.x);
                fma2(acc[bb][1], xv, w.y);
            }
        }
        #pragma unroll
        for (int bb = 0; bb < 8; bb++) {
            int b = bg * 8 + bb;
            float o0, o1, o2, o3;
            upk2(acc[bb][0], o0, o1);
            upk2(acc[bb][1], o2, o3);
            *(float4*)&g_xw[((size_t)t * BATCH + b) * NHID + h0] =
                make_float4(o0, o1, o2, o3);
        }
    }
}

// ---------------------------------------------------------------------------
// stage one 32 KB chunk (128 k x 64 b) into a swizzled smem buffer.
// global layout [b][k]; smem layout: row b = 128 floats, 16B granule g
// stored at granule (g XOR (b&31))  -> conflict-free LDS.128 later.
// ---------------------------------------------------------------------------
__device__ __forceinline__ void fill_chunk(const float* __restrict__ hySrc,
                                           int c, float* __restrict__ buf,
                                           int tid) {
    #pragma unroll
    for (int i = 0; i < 16; i++) {
        int G = tid + (i << 7);            // 0..2047
        int b = G >> 5, g = G & 31;
        const float* src = hySrc + ((size_t)b << 10) + (c << 7) + (g << 2);
        float*       dst = buf + (b << 7) + (((g ^ (b & 31)) & 31) << 2);
        cp_async16(dst, src);
    }
}

// ---------------------------------------------------------------------------
// pipelined split-K matvec: out4[q] = sum_k hy[b][k] * W[k][j0+q], q=0..3
// jq=0 handles k-halves [c*128, c*128+64), jq=1 the other half, per chunk.
// Cross-jq reduction through smem at the end. One __syncthreads per chunk.
// ---------------------------------------------------------------------------
__device__ __forceinline__ void matvec_split(const float* __restrict__ hySrc,
                                             const float* __restrict__ w_s,
                                             float* __restrict__ bufs,
                                             int tid, int b, int jq,
                                             unsigned tgt, float out4[4]) {
    unsigned long long acc[8];
    #pragma unroll
    for (int q = 0; q < 8; q++) acc[q] = 0ull;

    poll_flag(0, tgt); fill_chunk(hySrc, 0, bufs, tid);        cp_commit();
    poll_flag(1, tgt); fill_chunk(hySrc, 1, bufs + CHF, tid);  cp_commit();

    const int bx   = b & 31;
    const int gofs = jq << 4;          // granule offset: jq*16

    for (int c = 0; c < NCH; c++) {
        if (c < NCH - 2) {
            poll_flag(c + 2, tgt);
            fill_chunk(hySrc, c + 2, bufs + ((c + 2) & 3) * CHF, tid);
            cp_commit();
            cp_wait<2>();
        } else if (c == NCH - 2) {
            cp_wait<1>();
        } else {
            cp_wait<0>();
        }
        __syncthreads();

        const float* buf = bufs + (c & 3) * CHF;
        const float* hb  = buf + (b << 7);
        const float* wb  = w_s + (c << 7) + (jq << 6);   // [col][k] base

        #pragma unroll
        for (int g = 0; g < 16; g++) {
            int gg = gofs + g;
            ulonglong2 hv = *(const ulonglong2*)(hb + ((gg ^ bx) << 2));
            int k = g << 2;
            #pragma unroll
            for (int q = 0; q < 8; q++) {
                ulonglong2 wv = *(const ulonglong2*)(wb + (q << 10) + k);
                fma2(acc[q], hv.x, wv.x);
                fma2(acc[q], hv.y, wv.y);
            }
        }
    }

    // cross-jq reduction (reuse first 1 KB of buf0; all chunks done)
    float* red = bufs;
    __syncthreads();
    float part[8];
    #pragma unroll
    for (int q = 0; q < 8; q++) {
        float lo, hi; upk2(acc[q], lo, hi); part[q] = lo + hi;
    }
    float* myr = red + (jq << 9) + (b << 3);
    *(float4*)myr       = make_float4(part[0], part[1], part[2], part[3]);
    *(float4*)(myr + 4) = make_float4(part[4], part[5], part[6], part[7]);
    __syncthreads();
    const float4 s0 = *(const float4*)(red + (b << 3) + (jq << 2));
    const float4 s1 = *(const float4*)(red + 512 + (b << 3) + (jq << 2));
    out4[0] = s0.x + s1.x; out4[1] = s0.y + s1.y;
    out4[2] = s0.z + s1.z; out4[3] = s0.w + s1.w;
    __syncthreads();   // red area free again before next fills
}

// ---------------------------------------------------------------------------
// persistent harmonic kernel, flag-pipelined. grid=128, blk=128, smem=160 KB.
// ---------------------------------------------------------------------------
__global__ void __launch_bounds__(BLK_H, 1)
harm_persist(const float* __restrict__ W,
             const float* __restrict__ bias,
             const float* __restrict__ gamma,
             const float* __restrict__ epsv,
             float* __restrict__ hys,
             float* __restrict__ hzs) {
    extern __shared__ float sm[];
    float* w_s  = sm;              // [8 cols][1024 k]  32 KB
    float* bufs = sm + NHID * 8;   // 4 x 32 KB ring

    const int tid = threadIdx.x;
    const int b   = tid & 63;
    const int jq  = tid >> 6;
    const int J0  = blockIdx.x * 8;
    const int j0  = J0 + jq * 4;

    // one-time: W columns into smem, layout [local col][k]
    for (int i = tid; i < NHID * 8; i += BLK_H) {
        int cc = i & 7, k = i >> 3;
        w_s[cc * NHID + k] = W[(size_t)k * NHID + J0 + cc];
    }

    float4 bsv = *(const float4*)&bias[j0];
    float4 gmv = *(const float4*)&gamma[j0];
    float4 epv = *(const float4*)&epsv[j0];
    const float bs[4] = {bsv.x, bsv.y, bsv.z, bsv.w};
    const float gm[4] = {gmv.x, gmv.y, gmv.z, gmv.w};
    const float ep[4] = {epv.x, epv.y, epv.z, epv.w};

    float hy[4] = {0.f, 0.f, 0.f, 0.f};
    float hz[4] = {0.f, 0.f, 0.f, 0.f};

    __syncthreads();

    for (int t = 0; t < THARM; t++) {
        float a4[4] = {0.f, 0.f, 0.f, 0.f};
        if (t > 0)
            matvec_split(g_hyBK[(t - 1) & 1], w_s, bufs, tid, b, jq,
                         16u * (unsigned)t, a4);

        float4 xv = *(const float4*)&g_xw[((size_t)t * BATCH + b) * NHID + j0];
        const float xq[4] = {xv.x, xv.y, xv.z, xv.w};

        #pragma unroll
        for (int q = 0; q < 4; q++) {
            float pre = a4[q] + xq[q] + bs[q];
            float val = tanhf(pre);
            hz[q] = hz[q] + DTF * ((val - gm[q] * hy[q]) - ep[q] * hz[q]);
            hy[q] = hy[q] + DTF * hz[q];
        }

        // publish hy in natural [b][k] layout
        *(float4*)&g_hyBK[t & 1][(size_t)b * NHID + j0] =
            make_float4(hy[0], hy[1], hy[2], hy[3]);

        size_t o = ((size_t)b * TFULL + t) * NHID + j0;
        *(float4*)&hys[o] = make_float4(hy[0], hy[1], hy[2], hy[3]);
        *(float4*)&hzs[o] = make_float4(hz[0], hz[1], hz[2], hz[3]);

        __syncthreads();                       // CTA's stores all issued
        if (tid == 0) red_release(&g_flag[blockIdx.x >> 4]);
    }

    // final: hyW = hy(255) @ W   (buffer 1, epoch 256)
    {
        float a4[4];
        matvec_split(g_hyBK[1], w_s, bufs, tid, b, jq, 16u * 256u, a4);
        *(float4*)&g_hyW[(size_t)b * NHID + j0] =
            make_float4(a4[0], a4[1], a4[2], a4[3]);
        *(float4*)&g_hzF[(size_t)b * NHID + j0] =
            make_float4(hz[0], hz[1], hz[2], hz[3]);
    }
}

// ---------------------------------------------------------------------------
// spiking LIF phase + constant hy/hz tails. 4 h per thread, float4 I/O.
// grid = 64, block = 256  -> 16384 threads x 4 h.
// ---------------------------------------------------------------------------
__global__ void __launch_bounds__(256)
spike_kernel(float* __restrict__ us,
             float* __restrict__ spk,
             float* __restrict__ hys,
             float* __restrict__ hzs) {
    const int gid = blockIdx.x * 256 + threadIdx.x;  // 0..16383
    const int b   = gid >> 8;
    const int h0  = (gid & 255) << 2;
    const size_t base = (size_t)b * NHID + h0;

    const float4 hyw = *(const float4*)&g_hyW[base];
    const float4 hyf = *(const float4*)&g_hyBK[1][base];
    const float4 hzf = *(const float4*)&g_hzF[base];

    const float* xp  = g_xw + base;
    float* up  = us  + (size_t)b * TSPIKE * NHID + h0;
    float* sp  = spk + (size_t)b * TSPIKE * NHID + h0;
    float* hyp = hys + ((size_t)b * TFULL + THARM) * NHID + h0;
    float* hzp = hzs + ((size_t)b * TFULL + THARM) * NHID + h0;

    float u[4] = {0.f, 0.f, 0.f, 0.f};
    const float hw[4] = {hyw.x, hyw.y, hyw.z, hyw.w};

    #pragma unroll 4
    for (int t = 0; t < TSPIKE; t++) {
        float4 xin = *(const float4*)(xp + (size_t)t * BATCH * NHID);
        const float xq[4] = {xin.x, xin.y, xin.z, xin.w};
        float s[4];
        #pragma unroll
        for (int q = 0; q < 4; q++) {
            s[q] = (u[q] > THRESH) ? 1.0f : 0.0f;
            if (u[q] > THRESH) u[q] = RESETV;
            u[q] = u[q] + ((hw[q] + xq[q]) - u[q]) * LEAKC;
        }
        size_t to = (size_t)t * NHID;
        *(float4*)(up + to)  = make_float4(u[0], u[1], u[2], u[3]);
        *(float4*)(sp + to)  = make_float4(s[0], s[1], s[2], s[3]);
        *(float4*)(hyp + to) = hyf;
        *(float4*)(hzp + to) = hzf;
    }
}

// ---------------------------------------------------------------------------
// launcher: xw(+flag reset) -> persistent harmonic -> spike
// ---------------------------------------------------------------------------
extern "C" void kernel_launch(void* const* d_in, const int* in_sizes, int n_in,
                              void* d_out, int out_size) {
    const float* x    = (const float*)d_in[0];
    const float* x2h  = (const float*)d_in[1];
    const float* h2h  = (const float*)d_in[2];
    const float* bias = (const float*)d_in[3];
    const float* gam  = (const float*)d_in[4];
    const float* eps  = (const float*)d_in[5];

    float* out = (float*)d_out;
    float* hys = out;                                     // B*T*H
    float* hzs = hys + (size_t)BATCH * TFULL * NHID;      // B*T*H
    float* us  = hzs + (size_t)BATCH * TFULL * NHID;      // B*Ts*H
    float* spk = us  + (size_t)BATCH * TSPIKE * NHID;     // B*Ts*H

    static int smem_set = 0;
    const int smem_bytes = (NHID * 8 + 4 * CHF) * sizeof(float);  // 160 KB
    if (!smem_set) {
        cudaFuncSetAttribute(harm_persist,
                             cudaFuncAttributeMaxDynamicSharedMemorySize,
                             smem_bytes);
        smem_set = 1;
    }

    xw_kernel<<<THARM, 256>>>(x, x2h);
    harm_persist<<<GRID_H, BLK_H, smem_bytes>>>(h2h, bias, gam, eps, hys, hzs);
    spike_kernel<<<64, 256>>>(us, spk, hys, hzs);
}

// round 8
// speedup vs baseline: 3.8393x; 1.1461x over previous
#include <cuda_runtime.h>
#include <math.h>

// ---------------------------------------------------------------------------
// Problem constants
// ---------------------------------------------------------------------------
#define BATCH   64
#define TFULL   512
#define THARM   256
#define TSPIKE  256
#define NINP    64
#define NHID    1024
#define DTF     0.042f
#define THRESH  0.008f
#define RESETV  0.001f
#define LEAKC   0.00105f      /* R_MEM * C_MEM * DT */

#define GRID_H  128           /* persistent CTAs, 8 h-cols each            */
#define BLK_H   256           /* 8 warps; warp = distinct k-slice          */
#define NCH     8             /* chunks per step, 128 k each               */
#define CHF     8192          /* floats per chunk (128 k x 64 b) = 32 KB   */
#define REDS    520           /* padded per-warp stride in reduction area  */

// ---------------------------------------------------------------------------
// Device scratch (static — no cudaMalloc anywhere)
// ---------------------------------------------------------------------------
__device__ float    g_xw[(size_t)THARM * BATCH * NHID]; // x @ x2h  (64 MB)
__device__ float    g_hyBK[2][BATCH * NHID];            // hy state [b][k]
__device__ float    g_hzF[BATCH * NHID];                // final hz [b][h]
__device__ float    g_hyW[BATCH * NHID];                // hy_final @ h2h
__device__ unsigned g_flag[NCH];                        // per-chunk epochs

// ---------------------------------------------------------------------------
// packed f32x2 helpers
// ---------------------------------------------------------------------------
__device__ __forceinline__ void upk2(unsigned long long v, float &lo, float &hi) {
    asm("mov.b64 {%0, %1}, %2;" : "=f"(lo), "=f"(hi) : "l"(v));
}
__device__ __forceinline__ void fma2(unsigned long long &d,
                                     unsigned long long a,
                                     unsigned long long b) {
    asm("fma.rn.f32x2 %0, %1, %2, %0;" : "+l"(d) : "l"(a), "l"(b));
}

// ---------------------------------------------------------------------------
// async-copy / flag primitives
// ---------------------------------------------------------------------------
__device__ __forceinline__ void cp_async16(float* dst, const float* src) {
    unsigned d = (unsigned)__cvta_generic_to_shared(dst);
    asm volatile("cp.async.cg.shared.global [%0], [%1], 16;"
                 :: "r"(d), "l"(src));
}
__device__ __forceinline__ void cp_commit() {
    asm volatile("cp.async.commit_group;");
}
template<int N> __device__ __forceinline__ void cp_wait() {
    asm volatile("cp.async.wait_group %0;" :: "n"(N));
}
__device__ __forceinline__ unsigned ld_acq(const unsigned* p) {
    unsigned v;
    asm volatile("ld.acquire.gpu.global.u32 %0, [%1];" : "=r"(v) : "l"(p));
    return v;
}
__device__ __forceinline__ void red_release(unsigned* p) {
    asm volatile("red.release.gpu.global.add.u32 [%0], 1;" :: "l"(p));
}
__device__ __forceinline__ void poll_flag(int c, unsigned tgt) {
    if (ld_acq(&g_flag[c]) >= tgt) return;
    while (ld_acq(&g_flag[c]) < tgt) __nanosleep(40);
}

// ---------------------------------------------------------------------------
// xw[t][b][h] = x[b,t,:] @ x2h[:,h]  for t < 256.  grid=256, blk=256.
// Block 0 also resets the chunk flags for this launch (graph-replay safe).
// ---------------------------------------------------------------------------
__global__ void __launch_bounds__(256)
xw_kernel(const float* __restrict__ x, const float* __restrict__ x2h) {
    __shared__ float2 x_s[BATCH * NINP];

    const int t   = blockIdx.x;
    const int tid = threadIdx.x;

    if (blockIdx.x == 0 && tid < NCH) g_flag[tid] = 0u;

    for (int i = tid; i < BATCH * NINP; i += 256) {
        int b = i >> 6, ii = i & 63;
        float v = x[((size_t)b * TFULL + t) * NINP + ii];
        x_s[i] = make_float2(v, v);
    }
    __syncthreads();

    const int h0 = tid * 4;

    for (int bg = 0; bg < 8; bg++) {
        unsigned long long acc[8][2];
        #pragma unroll
        for (int bb = 0; bb < 8; bb++) { acc[bb][0] = 0ull; acc[bb][1] = 0ull; }

        #pragma unroll 4
        for (int k = 0; k < NINP; k++) {
            ulonglong2 w = *(const ulonglong2*)&x2h[k * NHID + h0];
            #pragma unroll
            for (int bb = 0; bb < 8; bb++) {
                unsigned long long xv =
                    *(const unsigned long long*)&x_s[(bg * 8 + bb) * NINP + k];
                fma2(acc[bb][0], xv, w.x);
                fma2(acc[bb][1], xv, w.y);
            }
        }
        #pragma unroll
        for (int bb = 0; bb < 8; bb++) {
            int b = bg * 8 + bb;
            float o0, o1, o2, o3;
            upk2(acc[bb][0], o0, o1);
            upk2(acc[bb][1], o2, o3);
            *(float4*)&g_xw[((size_t)t * BATCH + b) * NHID + h0] =
                make_float4(o0, o1, o2, o3);
        }
    }
}

// ---------------------------------------------------------------------------
// stage one 32 KB chunk cc (128 k x 64 b) into a swizzled smem buffer.
// global layout [b][k]; smem: row b = 128 floats, granule g stored at
// granule (g XOR (b&31)) -> conflict-free LDS.128 later.  256 threads.
// ---------------------------------------------------------------------------
__device__ __forceinline__ void fill_chunk(const float* __restrict__ hySrc,
                                           int cc, float* __restrict__ buf,
                                           int tid) {
    #pragma unroll
    for (int i = 0; i < 8; i++) {
        int G = tid + (i << 8);            // 0..2047
        int b = G >> 5, g = G & 31;
        const float* src = hySrc + ((size_t)b << 10) + (cc << 7) + (g << 2);
        float*       dst = buf + (b << 7) + (((g ^ (b & 31)) & 31) << 2);
        cp_async16(dst, src);
    }
}

// ---------------------------------------------------------------------------
// warp-sliced matvec: each of 8 warps owns a distinct 16-k slice per chunk
// (no duplicated W reads); lane = b (handles b and b+32), all 8 CTA cols.
// Chunk order staggered by 's'. Cross-warp reduction via padded smem.
// Outputs: o0 for (b = tid>>3, col = tid&7), o1 for (b+32, same col).
// ---------------------------------------------------------------------------
__device__ __forceinline__ void matvec256(const float* __restrict__ hySrc,
                                          const float* __restrict__ w_s,
                                          float* __restrict__ bufs,
                                          int tid, int lane, int wid, int s,
                                          unsigned tgt,
                                          float &o0, float &o1) {
    unsigned long long aA[8], aB[8];
    #pragma unroll
    for (int q = 0; q < 8; q++) { aA[q] = 0ull; aB[q] = 0ull; }

    poll_flag(s, tgt);           fill_chunk(hySrc, s,           bufs,       tid); cp_commit();
    poll_flag((s + 1) & 7, tgt); fill_chunk(hySrc, (s + 1) & 7, bufs + CHF, tid); cp_commit();

    for (int c = 0; c < NCH; c++) {
        const int cc = (s + c) & 7;
        if (c < NCH - 2) {
            const int cf = (s + c + 2) & 7;
            poll_flag(cf, tgt);
            fill_chunk(hySrc, cf, bufs + ((c + 2) & 3) * CHF, tid);
            cp_commit();
            cp_wait<2>();
        } else if (c == NCH - 2) {
            cp_wait<1>();
        } else {
            cp_wait<0>();
        }
        __syncthreads();

        const float* buf = bufs + (c & 3) * CHF;
        const float* hb0 = buf + (lane << 7);          // b = lane
        const float* hb1 = buf + ((lane + 32) << 7);   // b = lane+32
        const float* wb  = w_s + (cc << 7) + (wid << 4);

        #pragma unroll
        for (int i = 0; i < 4; i++) {
            const int g  = (wid << 2) + i;             // k-granule in chunk
            const int go = ((g ^ lane) & 31) << 2;
            ulonglong2 h0 = *(const ulonglong2*)(hb0 + go);
            ulonglong2 h1 = *(const ulonglong2*)(hb1 + go);
            #pragma unroll
            for (int q = 0; q < 8; q++) {
                ulonglong2 wv = *(const ulonglong2*)(wb + (q << 10) + (i << 2));
                fma2(aA[q], h0.x, wv.x);
                fma2(aA[q], h0.y, wv.y);
                fma2(aB[q], h1.x, wv.x);
                fma2(aB[q], h1.y, wv.y);
            }
        }
        // no trailing barrier: slot (c&3) is refilled at iteration c+2,
        // which every thread reaches only after the barrier of iteration c+1.
    }

    // ---- cross-warp reduction (reuse ring slot 0; disjoint from slot 3) ----
    float* red = bufs;    // 8 warps x REDS floats = 16.6 KB
    float pA[8], pB[8];
    #pragma unroll
    for (int q = 0; q < 8; q++) {
        float lo, hi;
        upk2(aA[q], lo, hi); pA[q] = lo + hi;
        upk2(aB[q], lo, hi); pB[q] = lo + hi;
    }
    float* myr = red + wid * REDS + (lane << 3);
    *(float4*)(myr)       = make_float4(pA[0], pA[1], pA[2], pA[3]);
    *(float4*)(myr + 4)   = make_float4(pA[4], pA[5], pA[6], pA[7]);
    *(float4*)(myr + 256) = make_float4(pB[0], pB[1], pB[2], pB[3]);
    *(float4*)(myr + 260) = make_float4(pB[4], pB[5], pB[6], pB[7]);
    __syncthreads();

    float s0 = 0.f, s1 = 0.f;
    #pragma unroll
    for (int w = 0; w < 8; w++) {
        s0 += red[w * REDS + tid];
        s1 += red[w * REDS + 256 + tid];
    }
    o0 = s0; o1 = s1;
    __syncthreads();   // red reads done before bufs is refilled next step
}

// ---------------------------------------------------------------------------
// persistent harmonic kernel. grid=128, blk=256, smem=160 KB.
// ---------------------------------------------------------------------------
__global__ void __launch_bounds__(BLK_H, 1)
harm_persist(const float* __restrict__ W,
             const float* __restrict__ bias,
             const float* __restrict__ gamma,
             const float* __restrict__ epsv,
             float* __restrict__ hys,
             float* __restrict__ hzs) {
    extern __shared__ float sm[];
    float* w_s  = sm;              // [8 cols][1024 k]  32 KB
    float* bufs = sm + NHID * 8;   // 4 x 32 KB ring

    const int tid  = threadIdx.x;
    const int lane = tid & 31;
    const int wid  = tid >> 5;
    const int J0   = blockIdx.x * 8;
    const int s    = blockIdx.x & 7;       // staggered chunk start

    // one-time: W columns into smem, layout [local col][k]
    for (int i = tid; i < NHID * 8; i += BLK_H) {
        int cc = i & 7, k = i >> 3;
        w_s[cc * NHID + k] = W[(size_t)k * NHID + J0 + cc];
    }

    // per-thread output ownership: (bA = tid>>3, col = J0 + (tid&7)), bB = bA+32
    const int bA = tid >> 3;
    const int bB = bA + 32;
    const int j  = J0 + (tid & 7);

    const float bs = bias[j];
    const float gm = gamma[j];
    const float ep = epsv[j];

    float hyA = 0.f, hzA = 0.f, hyB = 0.f, hzB = 0.f;

    __syncthreads();

    for (int t = 0; t < THARM; t++) {
        float o0 = 0.f, o1 = 0.f;
        if (t > 0)
            matvec256(g_hyBK[(t - 1) & 1], w_s, bufs, tid, lane, wid, s,
                      16u * (unsigned)t, o0, o1);

        const float xwA = g_xw[((size_t)t * BATCH + bA) * NHID + j];
        const float xwB = g_xw[((size_t)t * BATCH + bB) * NHID + j];

        float vA = tanhf(o0 + xwA + bs);
        float vB = tanhf(o1 + xwB + bs);
        hzA = hzA + DTF * ((vA - gm * hyA) - ep * hzA);
        hyA = hyA + DTF * hzA;
        hzB = hzB + DTF * ((vB - gm * hyB) - ep * hzB);
        hyB = hyB + DTF * hzB;

        // publish hy [b][k] for next step
        float* hyOut = g_hyBK[t & 1];
        hyOut[((size_t)bA << 10) + j] = hyA;
        hyOut[((size_t)bB << 10) + j] = hyB;

        // trajectory outputs (B, T, H)
        hys[((size_t)bA * TFULL + t) * NHID + j] = hyA;
        hzs[((size_t)bA * TFULL + t) * NHID + j] = hzA;
        hys[((size_t)bB * TFULL + t) * NHID + j] = hyB;
        hzs[((size_t)bB * TFULL + t) * NHID + j] = hzB;

        __syncthreads();                    // CTA's stores all issued
        if (tid == 0) red_release(&g_flag[blockIdx.x >> 4]);
    }

    // final: hyW = hy(255) @ W  (buffer 1, epoch 256)
    {
        float o0, o1;
        matvec256(g_hyBK[1], w_s, bufs, tid, lane, wid, s, 16u * 256u, o0, o1);
        g_hyW[((size_t)bA << 10) + j] = o0;
        g_hyW[((size_t)bB << 10) + j] = o1;
        g_hzF[((size_t)bA << 10) + j] = hzA;
        g_hzF[((size_t)bB << 10) + j] = hzB;
    }
}

// ---------------------------------------------------------------------------
// spiking LIF phase + constant hy/hz tails. 4 h per thread, float4 I/O.
// ---------------------------------------------------------------------------
__global__ void __launch_bounds__(256)
spike_kernel(float* __restrict__ us,
             float* __restrict__ spk,
             float* __restrict__ hys,
             float* __restrict__ hzs) {
    const int gid = blockIdx.x * 256 + threadIdx.x;  // 0..16383
    const int b   = gid >> 8;
    const int h0  = (gid & 255) << 2;
    const size_t base = (size_t)b * NHID + h0;

    const float4 hyw = *(const float4*)&g_hyW[base];
    const float4 hyf = *(const float4*)&g_hyBK[1][base];
    const float4 hzf = *(const float4*)&g_hzF[base];

    const float* xp  = g_xw + base;
    float* up  = us  + (size_t)b * TSPIKE * NHID + h0;
    float* sp  = spk + (size_t)b * TSPIKE * NHID + h0;
    float* hyp = hys + ((size_t)b * TFULL + THARM) * NHID + h0;
    float* hzp = hzs + ((size_t)b * TFULL + THARM) * NHID + h0;

    float u[4] = {0.f, 0.f, 0.f, 0.f};
    const float hw[4] = {hyw.x, hyw.y, hyw.z, hyw.w};

    #pragma unroll 4
    for (int t = 0; t < TSPIKE; t++) {
        float4 xin = *(const float4*)(xp + (size_t)t * BATCH * NHID);
        const float xq[4] = {xin.x, xin.y, xin.z, xin.w};
        float sv[4];
        #pragma unroll
        for (int q = 0; q < 4; q++) {
            sv[q] = (u[q] > THRESH) ? 1.0f : 0.0f;
            if (u[q] > THRESH) u[q] = RESETV;
            u[q] = u[q] + ((hw[q] + xq[q]) - u[q]) * LEAKC;
        }
        size_t to = (size_t)t * NHID;
        *(float4*)(up + to)  = make_float4(u[0], u[1], u[2], u[3]);
        *(float4*)(sp + to)  = make_float4(sv[0], sv[1], sv[2], sv[3]);
        *(float4*)(hyp + to) = hyf;
        *(float4*)(hzp + to) = hzf;
    }
}

// ---------------------------------------------------------------------------
// launcher: xw(+flag reset) -> persistent harmonic -> spike
// ---------------------------------------------------------------------------
extern "C" void kernel_launch(void* const* d_in, const int* in_sizes, int n_in,
                              void* d_out, int out_size) {
    const float* x    = (const float*)d_in[0];
    const float* x2h  = (const float*)d_in[1];
    const float* h2h  = (const float*)d_in[2];
    const float* bias = (const float*)d_in[3];
    const float* gam  = (const float*)d_in[4];
    const float* eps  = (const float*)d_in[5];

    float* out = (float*)d_out;
    float* hys = out;                                     // B*T*H
    float* hzs = hys + (size_t)BATCH * TFULL * NHID;      // B*T*H
    float* us  = hzs + (size_t)BATCH * TFULL * NHID;      // B*Ts*H
    float* spk = us  + (size_t)BATCH * TSPIKE * NHID;     // B*Ts*H

    static int smem_set = 0;
    const int smem_bytes = (NHID * 8 + 4 * CHF) * sizeof(float);  // 160 KB
    if (!smem_set) {
        cudaFuncSetAttribute(harm_persist,
                             cudaFuncAttributeMaxDynamicSharedMemorySize,
                             smem_bytes);
        smem_set = 1;
    }

    xw_kernel<<<THARM, 256>>>(x, x2h);
    harm_persist<<<GRID_H, BLK_H, smem_bytes>>>(h2h, bias, gam, eps, hys, hzs);
    spike_kernel<<<64, 256>>>(us, spk, hys, hzs);
}